// round 14
// baseline (speedup 1.0000x reference)
#include <cuda_runtime.h>
#include <cuda_fp16.h>
#include <math.h>
#include <stdint.h>

#define Bz    128
#define Sl    200
#define Dm    128
#define Hh    8
#define HD    16
#define Ll    2
#define DFF   2048
#define HID   512
#define TBLV  1000
#define IDXV  100000
#define TOUTN 8
#define NTOK  (Bz*Sl)   // 25600

// ================= scratch (device globals) =================
__device__ float  g_x   [2*NTOK*Dm];
__device__ __half g_qkv [2*NTOK*3*Dm];
__device__ __half g_hcath[Bz*2*Dm];
__device__ __half g_hh[Bz*HID];
__device__ __half g_xh [2*NTOK*Dm];
__device__ __half g_ath[2*NTOK*Dm];
__device__ __half g_ffh[(size_t)2*NTOK*DFF];
__device__ __half g_Wqkvh[2*Ll*3*Dm*Dm];
__device__ __half g_Woh  [2*Ll*Dm*Dm];
__device__ __half g_W1h  [2*Ll*DFF*Dm];
__device__ __half g_W2h  [2*Ll*Dm*DFF];
__device__ __half g_Wlinh[HID*2*Dm];

// ================= asm helpers (baseline PTX only) ==========
__device__ __forceinline__ uint32_t smem_u32(const void* p) {
    uint32_t a;
    asm("{ .reg .u64 t; cvta.to.shared.u64 t, %1; cvt.u32.u64 %0, t; }"
        : "=r"(a) : "l"(p));
    return a;
}
__device__ __forceinline__ void ldm_x4(uint32_t* r, uint32_t addr) {
    asm volatile("ldmatrix.sync.aligned.m8n8.x4.shared.b16 {%0,%1,%2,%3}, [%4];"
        : "=r"(r[0]), "=r"(r[1]), "=r"(r[2]), "=r"(r[3]) : "r"(addr));
}
__device__ __forceinline__ void mma16816(float* c, const uint32_t* a,
                                         uint32_t b0, uint32_t b1) {
    asm volatile("mma.sync.aligned.m16n8k16.row.col.f32.f16.f16.f32 "
        "{%0,%1,%2,%3}, {%4,%5,%6,%7}, {%8,%9}, {%0,%1,%2,%3};"
        : "+f"(c[0]), "+f"(c[1]), "+f"(c[2]), "+f"(c[3])
        : "r"(a[0]), "r"(a[1]), "r"(a[2]), "r"(a[3]), "r"(b0), "r"(b1));
}
#define CP16(dst, src) \
    asm volatile("cp.async.cg.shared.global [%0], [%1], 16;" :: "r"(dst), "l"(src))
#define CP_COMMIT() asm volatile("cp.async.commit_group;" ::: "memory")
#define CP_WAIT1()  asm volatile("cp.async.wait_group 1;" ::: "memory")
#define CP_WAIT0()  asm volatile("cp.async.wait_group 0;" ::: "memory")

__device__ __forceinline__ uint32_t pack_h2(float v0, float v1) {
    __half2 h = __halves2half2(__float2half_rn(v0), __float2half_rn(v1));
    return *(uint32_t*)&h;
}

// ================= small utility kernels =================
// merged weight converter: 5 segments in one launch
__global__ void cvt5_k(const float* s0, __half* d0, int n0,
                       const float* s1, __half* d1, int n1,
                       const float* s2, __half* d2, int n2,
                       const float* s3, __half* d3, int n3,
                       const float* s4, __half* d4, int n4)
{
    int i = blockIdx.x * 256 + threadIdx.x;
    int c0 = n0, c1 = c0 + n1, c2 = c1 + n2, c3 = c2 + n3, c4 = c3 + n4;
    if (i >= c4) return;
    if      (i < c0) d0[i]      = __float2half_rn(s0[i]);
    else if (i < c1) d1[i - c0] = __float2half_rn(s1[i - c0]);
    else if (i < c2) d2[i - c1] = __float2half_rn(s2[i - c1]);
    else if (i < c3) d3[i - c2] = __float2half_rn(s3[i - c2]);
    else             d4[i - c3] = __float2half_rn(s4[i - c3]);
}

__global__ void embed2_k(const int* __restrict__ ids0, const int* __restrict__ ids1,
                         const float* __restrict__ t0, const float* __restrict__ t1,
                         float* __restrict__ out, __half* __restrict__ oh)
{
    int z = blockIdx.y, n = blockIdx.x, d = threadIdx.x;
    const int*   ids = z ? ids1 : ids0;
    const float* tab = z ? t1   : t0;
    size_t o = ((size_t)z*NTOK + n)*Dm + d;
    float v = tab[(size_t)ids[n]*Dm + d];
    out[o] = v;
    oh[o] = __float2half_rn(v);
}

// ================= fp16 tensor-core GEMM ==============================
// C[M,N] = A[M,K] @ B[N,K]^T + bias.  A,B fp16, 1 MMA pass.
// Block tile 128x128, stage BK=32, 8 warps (4x2), warp tile 32x64.
// !CVTB: 3-stage cp.async ring (60KB) -> 2 CTAs/SM, one stage always in flight.
// CVTB : B raw fp32 [N, ldb] (ldb=K+1); 2-stage register path (projections).
// TOUT==8: time-broadcast epilogue, wlast = Bf[n*ldb + K].
// LNF  : requires N==128. x = LN(x + acc + bias); writes Cf=x, Ch=x fp16.
#define PITCH  80
#define TILEB  (128*PITCH)          // 10240
#define STG    (2*TILEB)            // 20480 per stage (A + B)
#define GSMEM  (3*STG)              // 61440

template<int TOUT, bool RELU, bool OUTH, bool CVTB, bool LNF>
__global__ __launch_bounds__(256, 2)
void gemm_mma(const __half* __restrict__ A,
              int lda, size_t sA,
              const __half* __restrict__ Bh16,
              const float* __restrict__ Bf,
              int ldb, size_t sB,
              const float* __restrict__ bias, size_t sBias,
              const float* __restrict__ gam, const float* __restrict__ bet,
              float* __restrict__ Cf, __half* __restrict__ Ch,
              int ldc, size_t sC, int N, int K)
{
    extern __shared__ __align__(16) char sm[];

    int tid  = threadIdx.x;
    int wid  = tid >> 5;
    int lane = tid & 31;
    int z = blockIdx.z;
    A += (size_t)z * sA;
    if (!CVTB) Bh16 += (size_t)z * sB;
    bias += (size_t)z * sBias;
    if (LNF) { gam += (size_t)z * sBias; bet += (size_t)z * sBias; }
    if (LNF)      { Cf += (size_t)z * sC; Ch += (size_t)z * sC; }
    else if (OUTH)  Ch += (size_t)z * sC;
    else            Cf += (size_t)z * sC;

    int m0 = blockIdx.y * 128;
    int n0 = blockIdx.x * 128;

    int lrow  = tid >> 1;
    int lhalf = tid & 1;
    int sdst = lrow*PITCH + lhalf*32;
    uint32_t sbase = smem_u32(sm);

    // compute mapping
    int wm = wid & 3;
    int wn = wid >> 2;
    int r8 = lane & 7, quad = lane >> 3;
    int arow = wm*32 + (quad & 1)*8 + r8;
    int aoff = (quad >> 1)*16;
    int brow = wn*64 + (quad >> 1)*8 + r8;
    int boff = (quad & 1)*16;

    float acc[2][8][4];
#pragma unroll
    for (int i = 0; i < 2; i++)
#pragma unroll
        for (int j = 0; j < 8; j++)
#pragma unroll
            for (int c = 0; c < 4; c++) acc[i][j][c] = 0.f;

    const int nst = K / 32;

    if (!CVTB) {
        const __half* gA = A + (size_t)(m0 + lrow)*lda + lhalf*16;
        const __half* gB = Bh16 + (size_t)(n0 + lrow)*ldb + lhalf*16;

#define ISSUE(s) do { \
        uint32_t st_ = sbase + ((s) % 3)*STG + sdst; \
        int k0_ = (s)*32; \
        CP16(st_,           gA + k0_); CP16(st_ + 16,          gA + k0_ + 8); \
        CP16(st_ + TILEB,   gB + k0_); CP16(st_ + TILEB + 16,  gB + k0_ + 8); \
        CP_COMMIT(); } while (0)

        ISSUE(0);
        if (nst > 1) ISSUE(1);

        for (int it = 0; it < nst; ++it) {
            if (it + 1 < nst) { CP_WAIT1(); } else { CP_WAIT0(); }
            __syncthreads();
            if (it + 2 < nst) ISSUE(it + 2);

            uint32_t stb = sbase + (it % 3)*STG;
            uint32_t bA = stb;
            uint32_t bB = stb + TILEB;
#pragma unroll
            for (int ks = 0; ks < 2; ks++) {
                int ko = ks * 32;
                uint32_t a4[2][4];
#pragma unroll
                for (int mi = 0; mi < 2; mi++)
                    ldm_x4(a4[mi], bA + (arow + mi*16)*PITCH + ko + aoff);
#pragma unroll
                for (int pj = 0; pj < 4; pj++) {
                    uint32_t b4[4];
                    ldm_x4(b4, bB + (brow + pj*16)*PITCH + ko + boff);
#pragma unroll
                    for (int mi = 0; mi < 2; mi++) {
                        mma16816(acc[mi][2*pj],   a4[mi], b4[0], b4[1]);
                        mma16816(acc[mi][2*pj+1], a4[mi], b4[2], b4[3]);
                    }
                }
            }
        }
#undef ISSUE
    } else {
        int browg = min(n0 + lrow, N - 1);
        const __half* gA = A + (size_t)(m0 + lrow)*lda + lhalf*16;
        const float* gB = Bf + (size_t)browg*ldb + lhalf*16;

        uint4 pa0, pa1;
        uint32_t pb[8];

        auto loadstage = [&](int k0) {
            pa0 = *(const uint4*)(gA + k0);
            pa1 = *(const uint4*)(gA + k0 + 8);
#pragma unroll
            for (int j = 0; j < 8; j++)
                pb[j] = pack_h2(gB[k0 + 2*j], gB[k0 + 2*j + 1]);
        };
        auto storestage = [&](int b) {
            char* stg = sm + b*STG;
            *(uint4*)(stg + sdst)              = pa0;
            *(uint4*)(stg + sdst + 16)         = pa1;
            *(uint4*)(stg + TILEB + sdst)      = make_uint4(pb[0],pb[1],pb[2],pb[3]);
            *(uint4*)(stg + TILEB + sdst + 16) = make_uint4(pb[4],pb[5],pb[6],pb[7]);
        };

        loadstage(0);
        storestage(0);

        for (int it = 0; it < nst; ++it) {
            int buf = it & 1;
            bool more = (it + 1) < nst;
            if (more) loadstage((it + 1) * 32);
            __syncthreads();

            uint32_t stb = sbase + buf*STG;
            uint32_t bA = stb;
            uint32_t bB = stb + TILEB;
#pragma unroll
            for (int ks = 0; ks < 2; ks++) {
                int ko = ks * 32;
                uint32_t a4[2][4];
#pragma unroll
                for (int mi = 0; mi < 2; mi++)
                    ldm_x4(a4[mi], bA + (arow + mi*16)*PITCH + ko + aoff);
#pragma unroll
                for (int pj = 0; pj < 4; pj++) {
                    uint32_t b4[4];
                    ldm_x4(b4, bB + (brow + pj*16)*PITCH + ko + boff);
#pragma unroll
                    for (int mi = 0; mi < 2; mi++) {
                        mma16816(acc[mi][2*pj],   a4[mi], b4[0], b4[1]);
                        mma16816(acc[mi][2*pj+1], a4[mi], b4[2], b4[3]);
                    }
                }
            }

            if (more) {
                __syncthreads();
                storestage(buf ^ 1);
            }
        }
    }

    // ---- epilogue ----
    int mrow0 = m0 + wm*32 + (lane >> 2);
    int ncol0 = n0 + wn*64 + (lane & 3)*2;

    if (LNF) {
        __syncthreads();                 // stage smem now reusable
        float* red = (float*)sm;         // [128 rows][8 partials][2]
        int rbase = wm*32 + (lane >> 2);
        int pcol = wn*4 + (lane & 3);

#pragma unroll
        for (int mi = 0; mi < 2; mi++)
#pragma unroll
        for (int half = 0; half < 2; half++) {
            int row = rbase + mi*16 + half*8;
            int grow = m0 + row;
            float s = 0.f, s2 = 0.f;
#pragma unroll
            for (int nj = 0; nj < 8; nj++) {
                int col = (lane & 3)*2 + wn*64 + nj*8;
                float2 res = *(const float2*)(Cf + (size_t)grow*ldc + col);
                float t0 = acc[mi][nj][2*half]     + bias[col]     + res.x;
                float t1 = acc[mi][nj][2*half + 1] + bias[col + 1] + res.y;
                acc[mi][nj][2*half]     = t0;
                acc[mi][nj][2*half + 1] = t1;
                s  += t0 + t1;
                s2 += t0*t0 + t1*t1;
            }
            red[(row*8 + pcol)*2]     = s;
            red[(row*8 + pcol)*2 + 1] = s2;
        }
        __syncthreads();

#pragma unroll
        for (int mi = 0; mi < 2; mi++)
#pragma unroll
        for (int half = 0; half < 2; half++) {
            int row = rbase + mi*16 + half*8;
            int grow = m0 + row;
            float s = 0.f, s2 = 0.f;
#pragma unroll
            for (int p = 0; p < 8; p++) {
                s  += red[(row*8 + p)*2];
                s2 += red[(row*8 + p)*2 + 1];
            }
            float mean = s * (1.f/128.f);
            float var  = s2 * (1.f/128.f) - mean*mean;
            float inv  = rsqrtf(var + 1e-5f);
#pragma unroll
            for (int nj = 0; nj < 8; nj++) {
                int col = (lane & 3)*2 + wn*64 + nj*8;
                float t0 = acc[mi][nj][2*half];
                float t1 = acc[mi][nj][2*half + 1];
                float y0 = (t0 - mean)*inv*gam[col]     + bet[col];
                float y1 = (t1 - mean)*inv*gam[col + 1] + bet[col + 1];
                float2 yv; yv.x = y0; yv.y = y1;
                *(float2*)(Cf + (size_t)grow*ldc + col) = yv;
                __half2 hp = __halves2half2(__float2half_rn(y0), __float2half_rn(y1));
                *(__half2*)(Ch + (size_t)grow*ldc + col) = hp;
            }
        }
        return;
    }

#pragma unroll
    for (int mi = 0; mi < 2; mi++) {
#pragma unroll
        for (int nj = 0; nj < 8; nj++) {
            int col = ncol0 + nj*8;
            if (CVTB && col >= N) continue;
            float b0 = bias[col], b1 = bias[col + 1];
            float w0 = 0.f, w1 = 0.f;
            if (TOUT > 1) {
                w0 = Bf[(size_t)col*ldb + K];
                w1 = Bf[(size_t)(col + 1)*ldb + K];
            }
#pragma unroll
            for (int half = 0; half < 2; half++) {
                int row = mrow0 + mi*16 + half*8;
                float v0 = acc[mi][nj][2*half]     + b0;
                float v1 = acc[mi][nj][2*half + 1] + b1;
                if (RELU) { v0 = fmaxf(v0, 0.f); v1 = fmaxf(v1, 0.f); }
                if (TOUT > 1) {
#pragma unroll
                    for (int tt = 0; tt < TOUTN; tt++) {
                        float2 v; v.x = v0 + tt*w0; v.y = v1 + tt*w1;
                        *(float2*)(Cf + (size_t)(row*TOUTN + tt)*ldc + col) = v;
                    }
                } else if (OUTH) {
                    __half2 hp = __halves2half2(__float2half_rn(v0), __float2half_rn(v1));
                    *(__half2*)(Ch + (size_t)row*ldc + col) = hp;
                } else {
                    float2 v; v.x = v0; v.y = v1;
                    *(float2*)(Cf + (size_t)row*ldc + col) = v;
                }
            }
        }
    }
}

// ========== attention (fp16 qkv in, fp32 math, fp16 out) ==========
__global__ __launch_bounds__(256)
void attn_k(const __half* __restrict__ qkv, __half* __restrict__ oh)
{
    int z = blockIdx.y;
    int bh = blockIdx.x;
    int b = bh / Hh, h = bh % Hh;
    __shared__ float ks[Sl][HD];
    __shared__ float vs[Sl][HD];
    int tid = threadIdx.x;
    const __half* base = qkv + ((size_t)z*NTOK + (size_t)b*Sl)*(3*Dm);

    for (int e = tid; e < Sl*HD; e += 256) {
        int s = e / HD, d = e % HD;
        ks[s][d] = __half2float(base[s*(3*Dm) + Dm   + h*HD + d]);
        vs[s][d] = __half2float(base[s*(3*Dm) + 2*Dm + h*HD + d]);
    }
    __syncthreads();

    if (tid < Sl) {
        int s = tid;
        float q[HD];
#pragma unroll
        for (int d = 0; d < HD; d++)
            q[d] = __half2float(base[s*(3*Dm) + h*HD + d]) * 0.25f;  // 1/sqrt(16)

        float m = -1e30f, l = 0.f;
        float acc[HD];
#pragma unroll
        for (int d = 0; d < HD; d++) acc[d] = 0.f;

        for (int j = 0; j < Sl; j++) {
            float sc = 0.f;
#pragma unroll
            for (int d = 0; d < HD; d++) sc = fmaf(q[d], ks[j][d], sc);
            float nm  = fmaxf(m, sc);
            float cor = __expf(m - nm);
            float p   = __expf(sc - nm);
            l = l*cor + p;
#pragma unroll
            for (int d = 0; d < HD; d++) acc[d] = acc[d]*cor + p*vs[j][d];
            m = nm;
        }
        float inv = 1.f / l;
        size_t o = ((size_t)z*NTOK + (size_t)b*Sl + s)*Dm + h*HD;
#pragma unroll
        for (int d = 0; d < HD; d++)
            oh[o + d] = __float2half_rn(acc[d]*inv);
    }
}

// ---------------- sequence mean into fp16 hcat --------------------------
__global__ void mean_k(const float* __restrict__ x, __half* __restrict__ oh)
{
    int z = blockIdx.y;
    int b = blockIdx.x, d = threadIdx.x;
    const float* xp = x + ((size_t)z*NTOK + (size_t)b*Sl)*Dm;
    float s = 0.f;
    for (int j = 0; j < Sl; j++) s += xp[j*Dm + d];
    oh[b*(2*Dm) + z*Dm + d] = __float2half_rn(s * (1.f/Sl));
}

// ================= launcher =================
extern "C" void kernel_launch(void* const* d_in, const int* in_sizes, int n_in,
                              void* d_out, int out_size)
{
    const int*   tid_seq = (const int*)  d_in[0];
    const int*   iid_seq = (const int*)  d_in[1];
    const float* tab_emb = (const float*)d_in[2];
    const float* idx_emb = (const float*)d_in[3];
    const float* Wqkv = (const float*)d_in[4];
    const float* bqkv = (const float*)d_in[5];
    const float* Wo   = (const float*)d_in[6];
    const float* bo   = (const float*)d_in[7];
    const float* ln1g = (const float*)d_in[8];
    const float* ln1b = (const float*)d_in[9];
    const float* W1   = (const float*)d_in[10];
    const float* b1   = (const float*)d_in[11];
    const float* W2   = (const float*)d_in[12];
    const float* b2   = (const float*)d_in[13];
    const float* ln2g = (const float*)d_in[14];
    const float* ln2b = (const float*)d_in[15];
    const float* Wlin = (const float*)d_in[16];
    const float* blin = (const float*)d_in[17];
    const float* Wtab = (const float*)d_in[18];
    const float* btab = (const float*)d_in[19];
    const float* Widx = (const float*)d_in[20];
    const float* bidx = (const float*)d_in[21];

    float* out     = (float*)d_out;
    float* out_tab = out;
    float* out_idx = out + (size_t)Bz*TOUTN*TBLV;

    float *x;
    __half *qkv, *xh, *ath, *ffh, *hcath, *hh;
    __half *Wqkvh, *Woh, *W1h, *W2h, *Wlinh;
    cudaGetSymbolAddress((void**)&x,    g_x);
    cudaGetSymbolAddress((void**)&qkv,  g_qkv);
    cudaGetSymbolAddress((void**)&xh,   g_xh);
    cudaGetSymbolAddress((void**)&ath,  g_ath);
    cudaGetSymbolAddress((void**)&ffh,  g_ffh);
    cudaGetSymbolAddress((void**)&hcath, g_hcath);
    cudaGetSymbolAddress((void**)&hh,   g_hh);
    cudaGetSymbolAddress((void**)&Wqkvh, g_Wqkvh);
    cudaGetSymbolAddress((void**)&Woh,   g_Woh);
    cudaGetSymbolAddress((void**)&W1h,   g_W1h);
    cudaGetSymbolAddress((void**)&W2h,   g_W2h);
    cudaGetSymbolAddress((void**)&Wlinh, g_Wlinh);

    cudaFuncSetAttribute(gemm_mma<1,false,true ,false,false>, cudaFuncAttributeMaxDynamicSharedMemorySize, GSMEM);
    cudaFuncSetAttribute(gemm_mma<1,false,false,false,true >, cudaFuncAttributeMaxDynamicSharedMemorySize, GSMEM);
    cudaFuncSetAttribute(gemm_mma<1,true, true, false,false>, cudaFuncAttributeMaxDynamicSharedMemorySize, GSMEM);
    cudaFuncSetAttribute(gemm_mma<TOUTN,false,false,true,false>, cudaFuncAttributeMaxDynamicSharedMemorySize, GSMEM);

    const int MT = NTOK / 128;  // 200
    const size_t sX   = (size_t)NTOK*Dm;
    const size_t sQKV = (size_t)NTOK*3*Dm;
    const size_t sFF  = (size_t)NTOK*DFF;

    // one merged weight-conversion launch
    {
        int n0 = 2*Ll*3*Dm*Dm, n1 = 2*Ll*Dm*Dm, n2 = 2*Ll*DFF*Dm,
            n3 = 2*Ll*Dm*DFF, n4 = HID*2*Dm;
        int tot = n0 + n1 + n2 + n3 + n4;
        cvt5_k<<<(tot + 255)/256, 256>>>(Wqkv, Wqkvh, n0, Wo, Woh, n1,
                                         W1, W1h, n2, W2, W2h, n3,
                                         Wlin, Wlinh, n4);
    }

    embed2_k<<<dim3(NTOK, 2), Dm>>>(tid_seq, iid_seq, tab_emb, idx_emb, x, xh);

    for (int l = 0; l < Ll; l++) {
        // qkv = x @ Wqkv^T + b  -> fp16
        gemm_mma<1,false,true,false,false><<<dim3(3, MT, 2), 256, GSMEM>>>(
            xh, Dm, sX,
            Wqkvh + (size_t)l*3*Dm*Dm, nullptr,
            Dm, (size_t)Ll*3*Dm*Dm,
            bqkv + (size_t)l*3*Dm, (size_t)Ll*3*Dm, nullptr, nullptr,
            nullptr, qkv, 3*Dm, sQKV, 3*Dm, Dm);

        attn_k<<<dim3(Bz*Hh, 2), 256>>>(qkv, ath);

        // x = LN(x + att @ Wo^T + bo)  -- fused epilogue
        gemm_mma<1,false,false,false,true><<<dim3(1, MT, 2), 256, GSMEM>>>(
            ath, Dm, sX,
            Woh + (size_t)l*Dm*Dm, nullptr,
            Dm, (size_t)Ll*Dm*Dm,
            bo + (size_t)l*Dm, (size_t)Ll*Dm,
            ln1g + (size_t)l*Dm, ln1b + (size_t)l*Dm,
            x, xh, Dm, sX, Dm, Dm);

        // ff = relu(x @ W1^T + b1) -> fp16
        gemm_mma<1,true,true,false,false><<<dim3(DFF/128, MT, 2), 256, GSMEM>>>(
            xh, Dm, sX,
            W1h + (size_t)l*DFF*Dm, nullptr,
            Dm, (size_t)Ll*DFF*Dm,
            b1 + (size_t)l*DFF, (size_t)Ll*DFF, nullptr, nullptr,
            nullptr, ffh, DFF, sFF, DFF, Dm);

        // x = LN(x + ff @ W2^T + b2)  -- fused epilogue
        gemm_mma<1,false,false,false,true><<<dim3(1, MT, 2), 256, GSMEM>>>(
            ffh, DFF, sFF,
            W2h + (size_t)l*Dm*DFF, nullptr,
            DFF, (size_t)Ll*Dm*DFF,
            b2 + (size_t)l*Dm, (size_t)Ll*Dm,
            ln2g + (size_t)l*Dm, ln2b + (size_t)l*Dm,
            x, xh, Dm, sX, Dm, DFF);
    }

    mean_k<<<dim3(Bz, 2), Dm>>>(x, hcath);

    // h = relu(hcat @ Wlin^T + blin) -> fp16   [128,512] K=256
    gemm_mma<1,true,true,false,false><<<dim3(HID/128, 1, 1), 256, GSMEM>>>(
        hcath, 2*Dm, 0, Wlinh, nullptr, 2*Dm, 0, blin, 0,
        nullptr, nullptr,
        nullptr, hh, HID, 0, HID, 2*Dm);

    // tab: [128,1000] + t-broadcast -> [1024,1000]
    gemm_mma<TOUTN,false,false,true,false><<<dim3((TBLV + 127)/128, 1, 1), 256, GSMEM>>>(
        hh, HID, 0, nullptr, Wtab, HID + 1, 0, btab, 0,
        nullptr, nullptr,
        out_tab, nullptr, TBLV, 0, TBLV, HID);

    // idx: [128,100000] + t-broadcast -> [1024,100000]
    gemm_mma<TOUTN,false,false,true,false><<<dim3((IDXV + 127)/128, 1, 1), 256, GSMEM>>>(
        hh, HID, 0, nullptr, Widx, HID + 1, 0, bidx, 0,
        nullptr, nullptr,
        out_idx, nullptr, IDXV, 0, IDXV, HID);
}

// round 15
// speedup vs baseline: 1.6885x; 1.6885x over previous
#include <cuda_runtime.h>
#include <cuda_fp16.h>
#include <math.h>
#include <stdint.h>

#define Bz    128
#define Sl    200
#define Dm    128
#define Hh    8
#define HD    16
#define Ll    2
#define DFF   2048
#define HID   512
#define TBLV  1000
#define IDXV  100000
#define TOUTN 8
#define NTOK  (Bz*Sl)   // 25600

// ================= scratch (device globals) =================
__device__ float  g_x   [2*NTOK*Dm];
__device__ __half g_qkv [2*NTOK*3*Dm];
__device__ __half g_hcath[Bz*2*Dm];
__device__ __half g_hh[Bz*HID];
__device__ __half g_xh [2*NTOK*Dm];
__device__ __half g_ath[2*NTOK*Dm];
__device__ __half g_ffh[(size_t)2*NTOK*DFF];
__device__ __half g_Wqkvh[2*Ll*3*Dm*Dm];
__device__ __half g_Woh  [2*Ll*Dm*Dm];
__device__ __half g_W1h  [2*Ll*DFF*Dm];
__device__ __half g_W2h  [2*Ll*Dm*DFF];
__device__ __half g_Wlinh[HID*2*Dm];

// ================= asm helpers (baseline PTX only) ==========
__device__ __forceinline__ uint32_t smem_u32(const void* p) {
    uint32_t a;
    asm("{ .reg .u64 t; cvta.to.shared.u64 t, %1; cvt.u32.u64 %0, t; }"
        : "=r"(a) : "l"(p));
    return a;
}
__device__ __forceinline__ void ldm_x4(uint32_t* r, uint32_t addr) {
    asm volatile("ldmatrix.sync.aligned.m8n8.x4.shared.b16 {%0,%1,%2,%3}, [%4];"
        : "=r"(r[0]), "=r"(r[1]), "=r"(r[2]), "=r"(r[3]) : "r"(addr));
}
__device__ __forceinline__ void mma16816(float* c, const uint32_t* a,
                                         uint32_t b0, uint32_t b1) {
    asm volatile("mma.sync.aligned.m16n8k16.row.col.f32.f16.f16.f32 "
        "{%0,%1,%2,%3}, {%4,%5,%6,%7}, {%8,%9}, {%0,%1,%2,%3};"
        : "+f"(c[0]), "+f"(c[1]), "+f"(c[2]), "+f"(c[3])
        : "r"(a[0]), "r"(a[1]), "r"(a[2]), "r"(a[3]), "r"(b0), "r"(b1));
}
#define CP16(dst, src) \
    asm volatile("cp.async.cg.shared.global [%0], [%1], 16;" :: "r"(dst), "l"(src))
#define CP_COMMIT() asm volatile("cp.async.commit_group;" ::: "memory")
#define CP_WAIT1()  asm volatile("cp.async.wait_group 1;" ::: "memory")
#define CP_WAIT0()  asm volatile("cp.async.wait_group 0;" ::: "memory")

__device__ __forceinline__ uint32_t pack_h2(float v0, float v1) {
    __half2 h = __halves2half2(__float2half_rn(v0), __float2half_rn(v1));
    return *(uint32_t*)&h;
}

// ================= small utility kernels =================
__global__ void cvt5_k(const float* s0, __half* d0, int n0,
                       const float* s1, __half* d1, int n1,
                       const float* s2, __half* d2, int n2,
                       const float* s3, __half* d3, int n3,
                       const float* s4, __half* d4, int n4)
{
    int i = blockIdx.x * 256 + threadIdx.x;
    int c0 = n0, c1 = c0 + n1, c2 = c1 + n2, c3 = c2 + n3, c4 = c3 + n4;
    if (i >= c4) return;
    if      (i < c0) d0[i]      = __float2half_rn(s0[i]);
    else if (i < c1) d1[i - c0] = __float2half_rn(s1[i - c0]);
    else if (i < c2) d2[i - c1] = __float2half_rn(s2[i - c1]);
    else if (i < c3) d3[i - c2] = __float2half_rn(s3[i - c2]);
    else             d4[i - c3] = __float2half_rn(s4[i - c3]);
}

__global__ void embed2_k(const int* __restrict__ ids0, const int* __restrict__ ids1,
                         const float* __restrict__ t0, const float* __restrict__ t1,
                         float* __restrict__ out, __half* __restrict__ oh)
{
    int z = blockIdx.y, n = blockIdx.x, d = threadIdx.x;
    const int*   ids = z ? ids1 : ids0;
    const float* tab = z ? t1   : t0;
    size_t o = ((size_t)z*NTOK + n)*Dm + d;
    float v = tab[(size_t)ids[n]*Dm + d];
    out[o] = v;
    oh[o] = __float2half_rn(v);
}

// ================= fp16 tensor-core GEMM ==============================
// C[M,N] = A[M,K] @ B[N,K]^T + bias.  A,B fp16, 1 MMA pass.
// Block tile 128x128, stage BK=32, 8 warps (4x2), warp tile 32x64.
// !CVTB: 3-stage cp.async ring (60KB) -> 2 CTAs/SM.
// CVTB : B raw fp32 [N, ldb]; 2-stage register path (projections).
// TOUT==8: time-broadcast epilogue, wlast = Bf[n*ldb + K].
// LNF  : requires N==128. x = LN(x + acc + bias); writes Cf=x, Ch=x fp16.
#define PITCH  80
#define TILEB  (128*PITCH)
#define STG    (2*TILEB)
#define GSMEM  (3*STG)

template<int TOUT, bool RELU, bool OUTH, bool CVTB, bool LNF>
__global__ __launch_bounds__(256, 2)
void gemm_mma(const __half* __restrict__ A,
              int lda, size_t sA,
              const __half* __restrict__ Bh16,
              const float* __restrict__ Bf,
              int ldb, size_t sB,
              const float* __restrict__ bias, size_t sBias,
              const float* __restrict__ gam, const float* __restrict__ bet,
              float* __restrict__ Cf, __half* __restrict__ Ch,
              int ldc, size_t sC, int N, int K)
{
    extern __shared__ __align__(16) char sm[];

    int tid  = threadIdx.x;
    int wid  = tid >> 5;
    int lane = tid & 31;
    int z = blockIdx.z;
    A += (size_t)z * sA;
    if (!CVTB) Bh16 += (size_t)z * sB;
    bias += (size_t)z * sBias;
    if (LNF) { gam += (size_t)z * sBias; bet += (size_t)z * sBias; }
    if (LNF)      { Cf += (size_t)z * sC; Ch += (size_t)z * sC; }
    else if (OUTH)  Ch += (size_t)z * sC;
    else            Cf += (size_t)z * sC;

    int m0 = blockIdx.y * 128;
    int n0 = blockIdx.x * 128;

    int lrow  = tid >> 1;
    int lhalf = tid & 1;
    int sdst = lrow*PITCH + lhalf*32;
    uint32_t sbase = smem_u32(sm);

    int wm = wid & 3;
    int wn = wid >> 2;
    int r8 = lane & 7, quad = lane >> 3;
    int arow = wm*32 + (quad & 1)*8 + r8;
    int aoff = (quad >> 1)*16;
    int brow = wn*64 + (quad >> 1)*8 + r8;
    int boff = (quad & 1)*16;

    float acc[2][8][4];
#pragma unroll
    for (int i = 0; i < 2; i++)
#pragma unroll
        for (int j = 0; j < 8; j++)
#pragma unroll
            for (int c = 0; c < 4; c++) acc[i][j][c] = 0.f;

    const int nst = K / 32;

    if (!CVTB) {
        const __half* gA = A + (size_t)(m0 + lrow)*lda + lhalf*16;
        const __half* gB = Bh16 + (size_t)(n0 + lrow)*ldb + lhalf*16;

#define ISSUE(s) do { \
        uint32_t st_ = sbase + ((s) % 3)*STG + sdst; \
        int k0_ = (s)*32; \
        CP16(st_,           gA + k0_); CP16(st_ + 16,          gA + k0_ + 8); \
        CP16(st_ + TILEB,   gB + k0_); CP16(st_ + TILEB + 16,  gB + k0_ + 8); \
        CP_COMMIT(); } while (0)

        ISSUE(0);
        if (nst > 1) ISSUE(1);

        for (int it = 0; it < nst; ++it) {
            if (it + 1 < nst) { CP_WAIT1(); } else { CP_WAIT0(); }
            __syncthreads();
            if (it + 2 < nst) ISSUE(it + 2);

            uint32_t stb = sbase + (it % 3)*STG;
            uint32_t bA = stb;
            uint32_t bB = stb + TILEB;
#pragma unroll
            for (int ks = 0; ks < 2; ks++) {
                int ko = ks * 32;
                uint32_t a4[2][4];
#pragma unroll
                for (int mi = 0; mi < 2; mi++)
                    ldm_x4(a4[mi], bA + (arow + mi*16)*PITCH + ko + aoff);
#pragma unroll
                for (int pj = 0; pj < 4; pj++) {
                    uint32_t b4[4];
                    ldm_x4(b4, bB + (brow + pj*16)*PITCH + ko + boff);
#pragma unroll
                    for (int mi = 0; mi < 2; mi++) {
                        mma16816(acc[mi][2*pj],   a4[mi], b4[0], b4[1]);
                        mma16816(acc[mi][2*pj+1], a4[mi], b4[2], b4[3]);
                    }
                }
            }
        }
#undef ISSUE
    } else {
        int browg = min(n0 + lrow, N - 1);
        const __half* gA = A + (size_t)(m0 + lrow)*lda + lhalf*16;
        const float* gB = Bf + (size_t)browg*ldb + lhalf*16;

        uint4 pa0, pa1;
        uint32_t pb[8];

        auto loadstage = [&](int k0) {
            pa0 = *(const uint4*)(gA + k0);
            pa1 = *(const uint4*)(gA + k0 + 8);
#pragma unroll
            for (int j = 0; j < 8; j++)
                pb[j] = pack_h2(gB[k0 + 2*j], gB[k0 + 2*j + 1]);
        };
        auto storestage = [&](int b) {
            char* stg = sm + b*STG;
            *(uint4*)(stg + sdst)              = pa0;
            *(uint4*)(stg + sdst + 16)         = pa1;
            *(uint4*)(stg + TILEB + sdst)      = make_uint4(pb[0],pb[1],pb[2],pb[3]);
            *(uint4*)(stg + TILEB + sdst + 16) = make_uint4(pb[4],pb[5],pb[6],pb[7]);
        };

        loadstage(0);
        storestage(0);

        for (int it = 0; it < nst; ++it) {
            int buf = it & 1;
            bool more = (it + 1) < nst;
            if (more) loadstage((it + 1) * 32);
            __syncthreads();

            uint32_t stb = sbase + buf*STG;
            uint32_t bA = stb;
            uint32_t bB = stb + TILEB;
#pragma unroll
            for (int ks = 0; ks < 2; ks++) {
                int ko = ks * 32;
                uint32_t a4[2][4];
#pragma unroll
                for (int mi = 0; mi < 2; mi++)
                    ldm_x4(a4[mi], bA + (arow + mi*16)*PITCH + ko + aoff);
#pragma unroll
                for (int pj = 0; pj < 4; pj++) {
                    uint32_t b4[4];
                    ldm_x4(b4, bB + (brow + pj*16)*PITCH + ko + boff);
#pragma unroll
                    for (int mi = 0; mi < 2; mi++) {
                        mma16816(acc[mi][2*pj],   a4[mi], b4[0], b4[1]);
                        mma16816(acc[mi][2*pj+1], a4[mi], b4[2], b4[3]);
                    }
                }
            }

            if (more) {
                __syncthreads();
                storestage(buf ^ 1);
            }
        }
    }

    // ---- epilogue ----
    int mrow0 = m0 + wm*32 + (lane >> 2);
    int ncol0 = n0 + wn*64 + (lane & 3)*2;

    if (LNF) {
        __syncthreads();
        float* red = (float*)sm;
        int rbase = wm*32 + (lane >> 2);
        int pcol = wn*4 + (lane & 3);

#pragma unroll
        for (int mi = 0; mi < 2; mi++)
#pragma unroll
        for (int half = 0; half < 2; half++) {
            int row = rbase + mi*16 + half*8;
            int grow = m0 + row;
            float s = 0.f, s2 = 0.f;
#pragma unroll
            for (int nj = 0; nj < 8; nj++) {
                int col = (lane & 3)*2 + wn*64 + nj*8;
                float2 res = *(const float2*)(Cf + (size_t)grow*ldc + col);
                float t0 = acc[mi][nj][2*half]     + bias[col]     + res.x;
                float t1 = acc[mi][nj][2*half + 1] + bias[col + 1] + res.y;
                acc[mi][nj][2*half]     = t0;
                acc[mi][nj][2*half + 1] = t1;
                s  += t0 + t1;
                s2 += t0*t0 + t1*t1;
            }
            red[(row*8 + pcol)*2]     = s;
            red[(row*8 + pcol)*2 + 1] = s2;
        }
        __syncthreads();

#pragma unroll
        for (int mi = 0; mi < 2; mi++)
#pragma unroll
        for (int half = 0; half < 2; half++) {
            int row = rbase + mi*16 + half*8;
            int grow = m0 + row;
            float s = 0.f, s2 = 0.f;
#pragma unroll
            for (int p = 0; p < 8; p++) {
                s  += red[(row*8 + p)*2];
                s2 += red[(row*8 + p)*2 + 1];
            }
            float mean = s * (1.f/128.f);
            float var  = s2 * (1.f/128.f) - mean*mean;
            float inv  = rsqrtf(var + 1e-5f);
#pragma unroll
            for (int nj = 0; nj < 8; nj++) {
                int col = (lane & 3)*2 + wn*64 + nj*8;
                float t0 = acc[mi][nj][2*half];
                float t1 = acc[mi][nj][2*half + 1];
                float y0 = (t0 - mean)*inv*gam[col]     + bet[col];
                float y1 = (t1 - mean)*inv*gam[col + 1] + bet[col + 1];
                float2 yv; yv.x = y0; yv.y = y1;
                *(float2*)(Cf + (size_t)grow*ldc + col) = yv;
                __half2 hp = __halves2half2(__float2half_rn(y0), __float2half_rn(y1));
                *(__half2*)(Ch + (size_t)grow*ldc + col) = hp;
            }
        }
        return;
    }

#pragma unroll
    for (int mi = 0; mi < 2; mi++) {
#pragma unroll
        for (int nj = 0; nj < 8; nj++) {
            int col = ncol0 + nj*8;
            if (CVTB && col >= N) continue;
            float b0 = bias[col], b1 = bias[col + 1];
            float w0 = 0.f, w1 = 0.f;
            if (TOUT > 1) {
                w0 = Bf[(size_t)col*ldb + K];
                w1 = Bf[(size_t)(col + 1)*ldb + K];
            }
#pragma unroll
            for (int half = 0; half < 2; half++) {
                int row = mrow0 + mi*16 + half*8;
                float v0 = acc[mi][nj][2*half]     + b0;
                float v1 = acc[mi][nj][2*half + 1] + b1;
                if (RELU) { v0 = fmaxf(v0, 0.f); v1 = fmaxf(v1, 0.f); }
                if (TOUT > 1) {
#pragma unroll
                    for (int tt = 0; tt < TOUTN; tt++) {
                        float2 v; v.x = v0 + tt*w0; v.y = v1 + tt*w1;
                        *(float2*)(Cf + (size_t)(row*TOUTN + tt)*ldc + col) = v;
                    }
                } else if (OUTH) {
                    __half2 hp = __halves2half2(__float2half_rn(v0), __float2half_rn(v1));
                    *(__half2*)(Ch + (size_t)row*ldc + col) = hp;
                } else {
                    float2 v; v.x = v0; v.y = v1;
                    *(float2*)(Cf + (size_t)row*ldc + col) = v;
                }
            }
        }
    }
}

// ========== attention: fp16 qkv in (VECTORIZED), fp32 math, fp16 out ==========
__global__ __launch_bounds__(256)
void attn_k(const __half* __restrict__ qkv, __half* __restrict__ oh)
{
    int z = blockIdx.y;
    int bh = blockIdx.x;
    int b = bh / Hh, h = bh % Hh;
    __shared__ float ks[Sl][HD];
    __shared__ float vs[Sl][HD];
    int tid = threadIdx.x;
    const __half* base = qkv + ((size_t)z*NTOK + (size_t)b*Sl)*(3*Dm);

    // K/V fill: uint4 loads (8 halves each), 2 chunks per row
    for (int e = tid; e < Sl*2; e += 256) {
        int s = e >> 1, c = e & 1;
        uint4 kv = *(const uint4*)(base + s*(3*Dm) + Dm   + h*HD + c*8);
        uint4 vv = *(const uint4*)(base + s*(3*Dm) + 2*Dm + h*HD + c*8);
        const __half2* kp = (const __half2*)&kv;
        const __half2* vp = (const __half2*)&vv;
#pragma unroll
        for (int i = 0; i < 4; i++) {
            float2 kf = __half22float2(kp[i]);
            float2 vf = __half22float2(vp[i]);
            ks[s][c*8 + 2*i]     = kf.x;
            ks[s][c*8 + 2*i + 1] = kf.y;
            vs[s][c*8 + 2*i]     = vf.x;
            vs[s][c*8 + 2*i + 1] = vf.y;
        }
    }
    __syncthreads();

    if (tid < Sl) {
        int s = tid;
        float q[HD];
        {
            uint4 q0 = *(const uint4*)(base + s*(3*Dm) + h*HD);
            uint4 q1 = *(const uint4*)(base + s*(3*Dm) + h*HD + 8);
            const __half2* qp0 = (const __half2*)&q0;
            const __half2* qp1 = (const __half2*)&q1;
#pragma unroll
            for (int i = 0; i < 4; i++) {
                float2 f0 = __half22float2(qp0[i]);
                float2 f1 = __half22float2(qp1[i]);
                q[2*i]     = f0.x * 0.25f;
                q[2*i + 1] = f0.y * 0.25f;
                q[8 + 2*i]     = f1.x * 0.25f;
                q[8 + 2*i + 1] = f1.y * 0.25f;
            }
        }

        float m = -1e30f, l = 0.f;
        float acc[HD];
#pragma unroll
        for (int d = 0; d < HD; d++) acc[d] = 0.f;

        for (int j = 0; j < Sl; j++) {
            float sc = 0.f;
#pragma unroll
            for (int d = 0; d < HD; d++) sc = fmaf(q[d], ks[j][d], sc);
            float nm  = fmaxf(m, sc);
            float cor = __expf(m - nm);
            float p   = __expf(sc - nm);
            l = l*cor + p;
#pragma unroll
            for (int d = 0; d < HD; d++) acc[d] = acc[d]*cor + p*vs[j][d];
            m = nm;
        }
        float inv = 1.f / l;
        size_t o = ((size_t)z*NTOK + (size_t)b*Sl + s)*Dm + h*HD;
        uint32_t pk[8];
#pragma unroll
        for (int i = 0; i < 8; i++)
            pk[i] = pack_h2(acc[2*i]*inv, acc[2*i + 1]*inv);
        *(uint4*)(oh + o)     = make_uint4(pk[0], pk[1], pk[2], pk[3]);
        *(uint4*)(oh + o + 8) = make_uint4(pk[4], pk[5], pk[6], pk[7]);
    }
}

// ---------------- sequence mean into fp16 hcat --------------------------
__global__ void mean_k(const float* __restrict__ x, __half* __restrict__ oh)
{
    int z = blockIdx.y;
    int b = blockIdx.x, d = threadIdx.x;
    const float* xp = x + ((size_t)z*NTOK + (size_t)b*Sl)*Dm;
    float s = 0.f;
    for (int j = 0; j < Sl; j++) s += xp[j*Dm + d];
    oh[b*(2*Dm) + z*Dm + d] = __float2half_rn(s * (1.f/Sl));
}

// ================= launcher =================
extern "C" void kernel_launch(void* const* d_in, const int* in_sizes, int n_in,
                              void* d_out, int out_size)
{
    const int*   tid_seq = (const int*)  d_in[0];
    const int*   iid_seq = (const int*)  d_in[1];
    const float* tab_emb = (const float*)d_in[2];
    const float* idx_emb = (const float*)d_in[3];
    const float* Wqkv = (const float*)d_in[4];
    const float* bqkv = (const float*)d_in[5];
    const float* Wo   = (const float*)d_in[6];
    const float* bo   = (const float*)d_in[7];
    const float* ln1g = (const float*)d_in[8];
    const float* ln1b = (const float*)d_in[9];
    const float* W1   = (const float*)d_in[10];
    const float* b1   = (const float*)d_in[11];
    const float* W2   = (const float*)d_in[12];
    const float* b2   = (const float*)d_in[13];
    const float* ln2g = (const float*)d_in[14];
    const float* ln2b = (const float*)d_in[15];
    const float* Wlin = (const float*)d_in[16];
    const float* blin = (const float*)d_in[17];
    const float* Wtab = (const float*)d_in[18];
    const float* btab = (const float*)d_in[19];
    const float* Widx = (const float*)d_in[20];
    const float* bidx = (const float*)d_in[21];

    float* out     = (float*)d_out;
    float* out_tab = out;
    float* out_idx = out + (size_t)Bz*TOUTN*TBLV;

    float *x;
    __half *qkv, *xh, *ath, *ffh, *hcath, *hh;
    __half *Wqkvh, *Woh, *W1h, *W2h, *Wlinh;
    cudaGetSymbolAddress((void**)&x,    g_x);
    cudaGetSymbolAddress((void**)&qkv,  g_qkv);
    cudaGetSymbolAddress((void**)&xh,   g_xh);
    cudaGetSymbolAddress((void**)&ath,  g_ath);
    cudaGetSymbolAddress((void**)&ffh,  g_ffh);
    cudaGetSymbolAddress((void**)&hcath, g_hcath);
    cudaGetSymbolAddress((void**)&hh,   g_hh);
    cudaGetSymbolAddress((void**)&Wqkvh, g_Wqkvh);
    cudaGetSymbolAddress((void**)&Woh,   g_Woh);
    cudaGetSymbolAddress((void**)&W1h,   g_W1h);
    cudaGetSymbolAddress((void**)&W2h,   g_W2h);
    cudaGetSymbolAddress((void**)&Wlinh, g_Wlinh);

    cudaFuncSetAttribute(gemm_mma<1,false,true ,false,false>, cudaFuncAttributeMaxDynamicSharedMemorySize, GSMEM);
    cudaFuncSetAttribute(gemm_mma<1,false,false,false,true >, cudaFuncAttributeMaxDynamicSharedMemorySize, GSMEM);
    cudaFuncSetAttribute(gemm_mma<1,true, true, false,false>, cudaFuncAttributeMaxDynamicSharedMemorySize, GSMEM);
    cudaFuncSetAttribute(gemm_mma<TOUTN,false,false,true,false>, cudaFuncAttributeMaxDynamicSharedMemorySize, GSMEM);

    const int MT = NTOK / 128;  // 200
    const size_t sX   = (size_t)NTOK*Dm;
    const size_t sQKV = (size_t)NTOK*3*Dm;
    const size_t sFF  = (size_t)NTOK*DFF;

    {
        int n0 = 2*Ll*3*Dm*Dm, n1 = 2*Ll*Dm*Dm, n2 = 2*Ll*DFF*Dm,
            n3 = 2*Ll*Dm*DFF, n4 = HID*2*Dm;
        int tot = n0 + n1 + n2 + n3 + n4;
        cvt5_k<<<(tot + 255)/256, 256>>>(Wqkv, Wqkvh, n0, Wo, Woh, n1,
                                         W1, W1h, n2, W2, W2h, n3,
                                         Wlin, Wlinh, n4);
    }

    embed2_k<<<dim3(NTOK, 2), Dm>>>(tid_seq, iid_seq, tab_emb, idx_emb, x, xh);

    for (int l = 0; l < Ll; l++) {
        // qkv = x @ Wqkv^T + b  -> fp16
        gemm_mma<1,false,true,false,false><<<dim3(3, MT, 2), 256, GSMEM>>>(
            xh, Dm, sX,
            Wqkvh + (size_t)l*3*Dm*Dm, nullptr,
            Dm, (size_t)Ll*3*Dm*Dm,
            bqkv + (size_t)l*3*Dm, (size_t)Ll*3*Dm, nullptr, nullptr,
            nullptr, qkv, 3*Dm, sQKV, 3*Dm, Dm);

        attn_k<<<dim3(Bz*Hh, 2), 256>>>(qkv, ath);

        // x = LN(x + att @ Wo^T + bo)  -- fused epilogue
        gemm_mma<1,false,false,false,true><<<dim3(1, MT, 2), 256, GSMEM>>>(
            ath, Dm, sX,
            Woh + (size_t)l*Dm*Dm, nullptr,
            Dm, (size_t)Ll*Dm*Dm,
            bo + (size_t)l*Dm, (size_t)Ll*Dm,
            ln1g + (size_t)l*Dm, ln1b + (size_t)l*Dm,
            x, xh, Dm, sX, Dm, Dm);

        // ff = relu(x @ W1^T + b1) -> fp16
        gemm_mma<1,true,true,false,false><<<dim3(DFF/128, MT, 2), 256, GSMEM>>>(
            xh, Dm, sX,
            W1h + (size_t)l*DFF*Dm, nullptr,
            Dm, (size_t)Ll*DFF*Dm,
            b1 + (size_t)l*DFF, (size_t)Ll*DFF, nullptr, nullptr,
            nullptr, ffh, DFF, sFF, DFF, Dm);

        // x = LN(x + ff @ W2^T + b2)  -- fused epilogue
        gemm_mma<1,false,false,false,true><<<dim3(1, MT, 2), 256, GSMEM>>>(
            ffh, DFF, sFF,
            W2h + (size_t)l*Dm*DFF, nullptr,
            DFF, (size_t)Ll*Dm*DFF,
            b2 + (size_t)l*Dm, (size_t)Ll*Dm,
            ln2g + (size_t)l*Dm, ln2b + (size_t)l*Dm,
            x, xh, Dm, sX, Dm, DFF);
    }

    mean_k<<<dim3(Bz, 2), Dm>>>(x, hcath);

    // h = relu(hcat @ Wlin^T + blin) -> fp16   [128,512] K=256
    gemm_mma<1,true,true,false,false><<<dim3(HID/128, 1, 1), 256, GSMEM>>>(
        hcath, 2*Dm, 0, Wlinh, nullptr, 2*Dm, 0, blin, 0,
        nullptr, nullptr,
        nullptr, hh, HID, 0, HID, 2*Dm);

    // tab: [128,1000] + t-broadcast -> [1024,1000]
    gemm_mma<TOUTN,false,false,true,false><<<dim3((TBLV + 127)/128, 1, 1), 256, GSMEM>>>(
        hh, HID, 0, nullptr, Wtab, HID + 1, 0, btab, 0,
        nullptr, nullptr,
        out_tab, nullptr, TBLV, 0, TBLV, HID);

    // idx: [128,100000] + t-broadcast -> [1024,100000]
    gemm_mma<TOUTN,false,false,true,false><<<dim3((IDXV + 127)/128, 1, 1), 256, GSMEM>>>(
        hh, HID, 0, nullptr, Widx, HID + 1, 0, bidx, 0,
        nullptr, nullptr,
        out_idx, nullptr, IDXV, 0, IDXV, HID);
}

// round 16
// speedup vs baseline: 2.2483x; 1.3316x over previous
#include <cuda_runtime.h>
#include <cuda_fp16.h>
#include <math.h>
#include <stdint.h>

#define Bz    128
#define Sl    200
#define Dm    128
#define Hh    8
#define HD    16
#define Ll    2
#define DFF   2048
#define HID   512
#define TBLV  1000
#define IDXV  100000
#define TOUTN 8
#define NTOK  (Bz*Sl)   // 25600
#define SLP   208       // Sl padded to 13*16

// ================= scratch (device globals) =================
__device__ float  g_x   [2*NTOK*Dm];
__device__ __half g_qkv [2*NTOK*3*Dm];
__device__ __half g_hcath[Bz*2*Dm];
__device__ __half g_hh[Bz*HID];
__device__ __half g_xh [2*NTOK*Dm];
__device__ __half g_ath[2*NTOK*Dm];
__device__ __half g_ffh[(size_t)2*NTOK*DFF];
__device__ __half g_Wqkvh[2*Ll*3*Dm*Dm];
__device__ __half g_Woh  [2*Ll*Dm*Dm];
__device__ __half g_W1h  [2*Ll*DFF*Dm];
__device__ __half g_W2h  [2*Ll*Dm*DFF];
__device__ __half g_Wlinh[HID*2*Dm];

// ================= asm helpers (baseline PTX only) ==========
__device__ __forceinline__ uint32_t smem_u32(const void* p) {
    uint32_t a;
    asm("{ .reg .u64 t; cvta.to.shared.u64 t, %1; cvt.u32.u64 %0, t; }"
        : "=r"(a) : "l"(p));
    return a;
}
__device__ __forceinline__ void ldm_x4(uint32_t* r, uint32_t addr) {
    asm volatile("ldmatrix.sync.aligned.m8n8.x4.shared.b16 {%0,%1,%2,%3}, [%4];"
        : "=r"(r[0]), "=r"(r[1]), "=r"(r[2]), "=r"(r[3]) : "r"(addr));
}
__device__ __forceinline__ void mma16816(float* c, const uint32_t* a,
                                         uint32_t b0, uint32_t b1) {
    asm volatile("mma.sync.aligned.m16n8k16.row.col.f32.f16.f16.f32 "
        "{%0,%1,%2,%3}, {%4,%5,%6,%7}, {%8,%9}, {%0,%1,%2,%3};"
        : "+f"(c[0]), "+f"(c[1]), "+f"(c[2]), "+f"(c[3])
        : "r"(a[0]), "r"(a[1]), "r"(a[2]), "r"(a[3]), "r"(b0), "r"(b1));
}
#define CP16(dst, src) \
    asm volatile("cp.async.cg.shared.global [%0], [%1], 16;" :: "r"(dst), "l"(src))
#define CP_COMMIT() asm volatile("cp.async.commit_group;" ::: "memory")
#define CP_WAIT1()  asm volatile("cp.async.wait_group 1;" ::: "memory")
#define CP_WAIT0()  asm volatile("cp.async.wait_group 0;" ::: "memory")

__device__ __forceinline__ uint32_t pack_h2(float v0, float v1) {
    __half2 h = __halves2half2(__float2half_rn(v0), __float2half_rn(v1));
    return *(uint32_t*)&h;
}

// ================= small utility kernels =================
__global__ void cvt5_k(const float* s0, __half* d0, int n0,
                       const float* s1, __half* d1, int n1,
                       const float* s2, __half* d2, int n2,
                       const float* s3, __half* d3, int n3,
                       const float* s4, __half* d4, int n4)
{
    int i = blockIdx.x * 256 + threadIdx.x;
    int c0 = n0, c1 = c0 + n1, c2 = c1 + n2, c3 = c2 + n3, c4 = c3 + n4;
    if (i >= c4) return;
    if      (i < c0) d0[i]      = __float2half_rn(s0[i]);
    else if (i < c1) d1[i - c0] = __float2half_rn(s1[i - c0]);
    else if (i < c2) d2[i - c1] = __float2half_rn(s2[i - c1]);
    else if (i < c3) d3[i - c2] = __float2half_rn(s3[i - c2]);
    else             d4[i - c3] = __float2half_rn(s4[i - c3]);
}

__global__ void embed2_k(const int* __restrict__ ids0, const int* __restrict__ ids1,
                         const float* __restrict__ t0, const float* __restrict__ t1,
                         float* __restrict__ out, __half* __restrict__ oh)
{
    int z = blockIdx.y, n = blockIdx.x, d = threadIdx.x;
    const int*   ids = z ? ids1 : ids0;
    const float* tab = z ? t1   : t0;
    size_t o = ((size_t)z*NTOK + n)*Dm + d;
    float v = tab[(size_t)ids[n]*Dm + d];
    out[o] = v;
    oh[o] = __float2half_rn(v);
}

// ================= fp16 tensor-core GEMM ==============================
#define PITCH  80
#define TILEB  (128*PITCH)
#define STG    (2*TILEB)
#define GSMEM  (3*STG)

template<int TOUT, bool RELU, bool OUTH, bool CVTB, bool LNF>
__global__ __launch_bounds__(256, 2)
void gemm_mma(const __half* __restrict__ A,
              int lda, size_t sA,
              const __half* __restrict__ Bh16,
              const float* __restrict__ Bf,
              int ldb, size_t sB,
              const float* __restrict__ bias, size_t sBias,
              const float* __restrict__ gam, const float* __restrict__ bet,
              float* __restrict__ Cf, __half* __restrict__ Ch,
              int ldc, size_t sC, int N, int K)
{
    extern __shared__ __align__(16) char sm[];

    int tid  = threadIdx.x;
    int wid  = tid >> 5;
    int lane = tid & 31;
    int z = blockIdx.z;
    A += (size_t)z * sA;
    if (!CVTB) Bh16 += (size_t)z * sB;
    bias += (size_t)z * sBias;
    if (LNF) { gam += (size_t)z * sBias; bet += (size_t)z * sBias; }
    if (LNF)      { Cf += (size_t)z * sC; Ch += (size_t)z * sC; }
    else if (OUTH)  Ch += (size_t)z * sC;
    else            Cf += (size_t)z * sC;

    int m0 = blockIdx.y * 128;
    int n0 = blockIdx.x * 128;

    int lrow  = tid >> 1;
    int lhalf = tid & 1;
    int sdst = lrow*PITCH + lhalf*32;
    uint32_t sbase = smem_u32(sm);

    int wm = wid & 3;
    int wn = wid >> 2;
    int r8 = lane & 7, quad = lane >> 3;
    int arow = wm*32 + (quad & 1)*8 + r8;
    int aoff = (quad >> 1)*16;
    int brow = wn*64 + (quad >> 1)*8 + r8;
    int boff = (quad & 1)*16;

    float acc[2][8][4];
#pragma unroll
    for (int i = 0; i < 2; i++)
#pragma unroll
        for (int j = 0; j < 8; j++)
#pragma unroll
            for (int c = 0; c < 4; c++) acc[i][j][c] = 0.f;

    const int nst = K / 32;

    if (!CVTB) {
        const __half* gA = A + (size_t)(m0 + lrow)*lda + lhalf*16;
        const __half* gB = Bh16 + (size_t)(n0 + lrow)*ldb + lhalf*16;

#define ISSUE(s) do { \
        uint32_t st_ = sbase + ((s) % 3)*STG + sdst; \
        int k0_ = (s)*32; \
        CP16(st_,           gA + k0_); CP16(st_ + 16,          gA + k0_ + 8); \
        CP16(st_ + TILEB,   gB + k0_); CP16(st_ + TILEB + 16,  gB + k0_ + 8); \
        CP_COMMIT(); } while (0)

        ISSUE(0);
        if (nst > 1) ISSUE(1);

        for (int it = 0; it < nst; ++it) {
            if (it + 1 < nst) { CP_WAIT1(); } else { CP_WAIT0(); }
            __syncthreads();
            if (it + 2 < nst) ISSUE(it + 2);

            uint32_t stb = sbase + (it % 3)*STG;
            uint32_t bA = stb;
            uint32_t bB = stb + TILEB;
#pragma unroll
            for (int ks = 0; ks < 2; ks++) {
                int ko = ks * 32;
                uint32_t a4[2][4];
#pragma unroll
                for (int mi = 0; mi < 2; mi++)
                    ldm_x4(a4[mi], bA + (arow + mi*16)*PITCH + ko + aoff);
#pragma unroll
                for (int pj = 0; pj < 4; pj++) {
                    uint32_t b4[4];
                    ldm_x4(b4, bB + (brow + pj*16)*PITCH + ko + boff);
#pragma unroll
                    for (int mi = 0; mi < 2; mi++) {
                        mma16816(acc[mi][2*pj],   a4[mi], b4[0], b4[1]);
                        mma16816(acc[mi][2*pj+1], a4[mi], b4[2], b4[3]);
                    }
                }
            }
        }
#undef ISSUE
    } else {
        int browg = min(n0 + lrow, N - 1);
        const __half* gA = A + (size_t)(m0 + lrow)*lda + lhalf*16;
        const float* gB = Bf + (size_t)browg*ldb + lhalf*16;

        uint4 pa0, pa1;
        uint32_t pb[8];

        auto loadstage = [&](int k0) {
            pa0 = *(const uint4*)(gA + k0);
            pa1 = *(const uint4*)(gA + k0 + 8);
#pragma unroll
            for (int j = 0; j < 8; j++)
                pb[j] = pack_h2(gB[k0 + 2*j], gB[k0 + 2*j + 1]);
        };
        auto storestage = [&](int b) {
            char* stg = sm + b*STG;
            *(uint4*)(stg + sdst)              = pa0;
            *(uint4*)(stg + sdst + 16)         = pa1;
            *(uint4*)(stg + TILEB + sdst)      = make_uint4(pb[0],pb[1],pb[2],pb[3]);
            *(uint4*)(stg + TILEB + sdst + 16) = make_uint4(pb[4],pb[5],pb[6],pb[7]);
        };

        loadstage(0);
        storestage(0);

        for (int it = 0; it < nst; ++it) {
            int buf = it & 1;
            bool more = (it + 1) < nst;
            if (more) loadstage((it + 1) * 32);
            __syncthreads();

            uint32_t stb = sbase + buf*STG;
            uint32_t bA = stb;
            uint32_t bB = stb + TILEB;
#pragma unroll
            for (int ks = 0; ks < 2; ks++) {
                int ko = ks * 32;
                uint32_t a4[2][4];
#pragma unroll
                for (int mi = 0; mi < 2; mi++)
                    ldm_x4(a4[mi], bA + (arow + mi*16)*PITCH + ko + aoff);
#pragma unroll
                for (int pj = 0; pj < 4; pj++) {
                    uint32_t b4[4];
                    ldm_x4(b4, bB + (brow + pj*16)*PITCH + ko + boff);
#pragma unroll
                    for (int mi = 0; mi < 2; mi++) {
                        mma16816(acc[mi][2*pj],   a4[mi], b4[0], b4[1]);
                        mma16816(acc[mi][2*pj+1], a4[mi], b4[2], b4[3]);
                    }
                }
            }

            if (more) {
                __syncthreads();
                storestage(buf ^ 1);
            }
        }
    }

    // ---- epilogue ----
    int mrow0 = m0 + wm*32 + (lane >> 2);
    int ncol0 = n0 + wn*64 + (lane & 3)*2;

    if (LNF) {
        __syncthreads();
        float* red = (float*)sm;
        int rbase = wm*32 + (lane >> 2);
        int pcol = wn*4 + (lane & 3);

#pragma unroll
        for (int mi = 0; mi < 2; mi++)
#pragma unroll
        for (int half = 0; half < 2; half++) {
            int row = rbase + mi*16 + half*8;
            int grow = m0 + row;
            float s = 0.f, s2 = 0.f;
#pragma unroll
            for (int nj = 0; nj < 8; nj++) {
                int col = (lane & 3)*2 + wn*64 + nj*8;
                float2 res = *(const float2*)(Cf + (size_t)grow*ldc + col);
                float t0 = acc[mi][nj][2*half]     + bias[col]     + res.x;
                float t1 = acc[mi][nj][2*half + 1] + bias[col + 1] + res.y;
                acc[mi][nj][2*half]     = t0;
                acc[mi][nj][2*half + 1] = t1;
                s  += t0 + t1;
                s2 += t0*t0 + t1*t1;
            }
            red[(row*8 + pcol)*2]     = s;
            red[(row*8 + pcol)*2 + 1] = s2;
        }
        __syncthreads();

#pragma unroll
        for (int mi = 0; mi < 2; mi++)
#pragma unroll
        for (int half = 0; half < 2; half++) {
            int row = rbase + mi*16 + half*8;
            int grow = m0 + row;
            float s = 0.f, s2 = 0.f;
#pragma unroll
            for (int p = 0; p < 8; p++) {
                s  += red[(row*8 + p)*2];
                s2 += red[(row*8 + p)*2 + 1];
            }
            float mean = s * (1.f/128.f);
            float var  = s2 * (1.f/128.f) - mean*mean;
            float inv  = rsqrtf(var + 1e-5f);
#pragma unroll
            for (int nj = 0; nj < 8; nj++) {
                int col = (lane & 3)*2 + wn*64 + nj*8;
                float t0 = acc[mi][nj][2*half];
                float t1 = acc[mi][nj][2*half + 1];
                float y0 = (t0 - mean)*inv*gam[col]     + bet[col];
                float y1 = (t1 - mean)*inv*gam[col + 1] + bet[col + 1];
                float2 yv; yv.x = y0; yv.y = y1;
                *(float2*)(Cf + (size_t)grow*ldc + col) = yv;
                __half2 hp = __halves2half2(__float2half_rn(y0), __float2half_rn(y1));
                *(__half2*)(Ch + (size_t)grow*ldc + col) = hp;
            }
        }
        return;
    }

#pragma unroll
    for (int mi = 0; mi < 2; mi++) {
#pragma unroll
        for (int nj = 0; nj < 8; nj++) {
            int col = ncol0 + nj*8;
            if (CVTB && col >= N) continue;
            float b0 = bias[col], b1 = bias[col + 1];
            float w0 = 0.f, w1 = 0.f;
            if (TOUT > 1) {
                w0 = Bf[(size_t)col*ldb + K];
                w1 = Bf[(size_t)(col + 1)*ldb + K];
            }
#pragma unroll
            for (int half = 0; half < 2; half++) {
                int row = mrow0 + mi*16 + half*8;
                float v0 = acc[mi][nj][2*half]     + b0;
                float v1 = acc[mi][nj][2*half + 1] + b1;
                if (RELU) { v0 = fmaxf(v0, 0.f); v1 = fmaxf(v1, 0.f); }
                if (TOUT > 1) {
#pragma unroll
                    for (int tt = 0; tt < TOUTN; tt++) {
                        float2 v; v.x = v0 + tt*w0; v.y = v1 + tt*w1;
                        *(float2*)(Cf + (size_t)(row*TOUTN + tt)*ldc + col) = v;
                    }
                } else if (OUTH) {
                    __half2 hp = __halves2half2(__float2half_rn(v0), __float2half_rn(v1));
                    *(__half2*)(Ch + (size_t)row*ldc + col) = hp;
                } else {
                    float2 v; v.x = v0; v.y = v1;
                    *(float2*)(Cf + (size_t)row*ldc + col) = v;
                }
            }
        }
    }
}

// ========== flash attention: tensor-core, fp16 in/out, fp32 accumulate =======
// One block per (z, b, h). 13 warps x 16 query rows. 13 key-tiles of 16.
// Q,K smem pitch 48B (conflict-free ldmatrix); V transposed, pitch 432B.
#define QK_PITCH 48
#define VT_PITCH 432
#define ATT_THREADS 416

__global__ __launch_bounds__(ATT_THREADS)
void attn_k(const __half* __restrict__ qkv, __half* __restrict__ oh)
{
    __shared__ __align__(16) char smq[SLP*QK_PITCH];
    __shared__ __align__(16) char smk[SLP*QK_PITCH];
    __shared__ __align__(16) char smv[HD*VT_PITCH];

    int z = blockIdx.y;
    int bh = blockIdx.x;
    int b = bh / Hh, h = bh % Hh;
    int tid = threadIdx.x;
    const __half* base = qkv + ((size_t)z*NTOK + (size_t)b*Sl)*(3*Dm) + h*HD;

    // ---- load Q, K (x0.25) : 416 threads = 208 rows x 2 halves ----
    {
        int row = tid >> 1, half = tid & 1;
        uint4 zv = make_uint4(0,0,0,0);
        uint4 qv = zv, kv = zv;
        if (row < Sl) {
            qv = *(const uint4*)(base + (size_t)row*(3*Dm) + half*8);
            kv = *(const uint4*)(base + (size_t)row*(3*Dm) + Dm + half*8);
            // scale K by 0.25 (fold 1/sqrt(hd) into K)
            __half2 sc = __half2half2(__float2half(0.25f));
            __half2* kp = (__half2*)&kv;
#pragma unroll
            for (int i = 0; i < 4; i++) kp[i] = __hmul2(kp[i], sc);
        }
        *(uint4*)(smq + row*QK_PITCH + half*16) = qv;
        *(uint4*)(smk + row*QK_PITCH + half*16) = kv;
    }
    // ---- load V transposed: Vt[d][j] ----
    for (int e = tid; e < SLP*2; e += ATT_THREADS) {
        int j = e >> 1, half = e & 1;
        if (j < Sl) {
            uint4 vv = *(const uint4*)(base + (size_t)j*(3*Dm) + 2*Dm + half*8);
            const __half* vp = (const __half*)&vv;
#pragma unroll
            for (int i = 0; i < 8; i++)
                *(__half*)(smv + (half*8 + i)*VT_PITCH + j*2) = vp[i];
        } else {
#pragma unroll
            for (int i = 0; i < 8; i++)
                *(__half*)(smv + (half*8 + i)*VT_PITCH + j*2) = __float2half(0.f);
        }
    }
    __syncthreads();

    int w    = tid >> 5;
    int lane = tid & 31;
    int r8 = lane & 7, quad = lane >> 3;
    uint32_t qb = smem_u32(smq);
    uint32_t kb = smem_u32(smk);
    uint32_t vb = smem_u32(smv);

    // Q fragment (m16k16), rows w*16..w*16+15
    uint32_t qf[4];
    ldm_x4(qf, qb + (w*16 + (quad & 1)*8 + r8)*QK_PITCH + (quad >> 1)*16);

    float m_r = -1e30f, m_s = -1e30f, l_r = 0.f, l_s = 0.f;
    float o0[4] = {0,0,0,0}, o1[4] = {0,0,0,0};   // d 0-7, d 8-15

    for (int t = 0; t < 13; t++) {
        uint32_t kf[4];
        ldm_x4(kf, kb + (t*16 + (quad >> 1)*8 + r8)*QK_PITCH + (quad & 1)*16);
        float s0[4] = {0,0,0,0}, s1[4] = {0,0,0,0};
        mma16816(s0, qf, kf[0], kf[1]);            // cols j = t*16 + 0..7
        bool full = (t < 12);
        if (full) mma16816(s1, qf, kf[2], kf[3]);  // cols j = t*16 + 8..15

        float mx_r = fmaxf(s0[0], s0[1]);
        float mx_s = fmaxf(s0[2], s0[3]);
        if (full) {
            mx_r = fmaxf(mx_r, fmaxf(s1[0], s1[1]));
            mx_s = fmaxf(mx_s, fmaxf(s1[2], s1[3]));
        }
        mx_r = fmaxf(mx_r, __shfl_xor_sync(0xffffffffu, mx_r, 1));
        mx_r = fmaxf(mx_r, __shfl_xor_sync(0xffffffffu, mx_r, 2));
        mx_s = fmaxf(mx_s, __shfl_xor_sync(0xffffffffu, mx_s, 1));
        mx_s = fmaxf(mx_s, __shfl_xor_sync(0xffffffffu, mx_s, 2));

        float nm_r = fmaxf(m_r, mx_r);
        float nm_s = fmaxf(m_s, mx_s);
        float cr = __expf(m_r - nm_r);
        float cs = __expf(m_s - nm_s);
        m_r = nm_r; m_s = nm_s;

        float p0[4], p1[4];
        p0[0] = __expf(s0[0] - nm_r); p0[1] = __expf(s0[1] - nm_r);
        p0[2] = __expf(s0[2] - nm_s); p0[3] = __expf(s0[3] - nm_s);
        if (full) {
            p1[0] = __expf(s1[0] - nm_r); p1[1] = __expf(s1[1] - nm_r);
            p1[2] = __expf(s1[2] - nm_s); p1[3] = __expf(s1[3] - nm_s);
        } else {
            p1[0] = p1[1] = p1[2] = p1[3] = 0.f;
        }

        l_r = l_r*cr + p0[0] + p0[1] + p1[0] + p1[1];
        l_s = l_s*cs + p0[2] + p0[3] + p1[2] + p1[3];

        o0[0] *= cr; o0[1] *= cr; o0[2] *= cs; o0[3] *= cs;
        o1[0] *= cr; o1[1] *= cr; o1[2] *= cs; o1[3] *= cs;

        // C-fragment == A-fragment layout: pack P
        uint32_t pf[4];
        pf[0] = pack_h2(p0[0], p0[1]);   // row r,   k = 2c, 2c+1
        pf[1] = pack_h2(p0[2], p0[3]);   // row r+8, k = 2c, 2c+1
        pf[2] = pack_h2(p1[0], p1[1]);   // row r,   k = 2c+8
        pf[3] = pack_h2(p1[2], p1[3]);   // row r+8, k = 2c+8

        uint32_t vf[4];
        ldm_x4(vf, vb + ((quad >> 1)*8 + r8)*VT_PITCH + t*32 + (quad & 1)*16);
        mma16816(o0, pf, vf[0], vf[1]);   // d 0-7
        mma16816(o1, pf, vf[2], vf[3]);   // d 8-15
    }

    // row-sum l across the quad
    l_r += __shfl_xor_sync(0xffffffffu, l_r, 1);
    l_r += __shfl_xor_sync(0xffffffffu, l_r, 2);
    l_s += __shfl_xor_sync(0xffffffffu, l_s, 1);
    l_s += __shfl_xor_sync(0xffffffffu, l_s, 2);
    float ir = 1.f / l_r;
    float is = 1.f / l_s;

    int q0 = w*16 + (lane >> 2);
    int c0 = (lane & 3)*2;
    size_t ob = ((size_t)z*NTOK + (size_t)b*Sl)*Dm + h*HD;
    if (q0 < Sl) {
        *(__half2*)(oh + ob + (size_t)q0*Dm + c0)     = *(__half2*)&(uint32_t){pack_h2(o0[0]*ir, o0[1]*ir)};
        *(__half2*)(oh + ob + (size_t)q0*Dm + 8 + c0) = *(__half2*)&(uint32_t){pack_h2(o1[0]*ir, o1[1]*ir)};
    }
    if (q0 + 8 < Sl) {
        *(__half2*)(oh + ob + (size_t)(q0+8)*Dm + c0)     = *(__half2*)&(uint32_t){pack_h2(o0[2]*is, o0[3]*is)};
        *(__half2*)(oh + ob + (size_t)(q0+8)*Dm + 8 + c0) = *(__half2*)&(uint32_t){pack_h2(o1[2]*is, o1[3]*is)};
    }
}

// ---------------- sequence mean into fp16 hcat --------------------------
__global__ void mean_k(const float* __restrict__ x, __half* __restrict__ oh)
{
    int z = blockIdx.y;
    int b = blockIdx.x, d = threadIdx.x;
    const float* xp = x + ((size_t)z*NTOK + (size_t)b*Sl)*Dm;
    float s = 0.f;
    for (int j = 0; j < Sl; j++) s += xp[j*Dm + d];
    oh[b*(2*Dm) + z*Dm + d] = __float2half_rn(s * (1.f/Sl));
}

// ================= launcher =================
extern "C" void kernel_launch(void* const* d_in, const int* in_sizes, int n_in,
                              void* d_out, int out_size)
{
    const int*   tid_seq = (const int*)  d_in[0];
    const int*   iid_seq = (const int*)  d_in[1];
    const float* tab_emb = (const float*)d_in[2];
    const float* idx_emb = (const float*)d_in[3];
    const float* Wqkv = (const float*)d_in[4];
    const float* bqkv = (const float*)d_in[5];
    const float* Wo   = (const float*)d_in[6];
    const float* bo   = (const float*)d_in[7];
    const float* ln1g = (const float*)d_in[8];
    const float* ln1b = (const float*)d_in[9];
    const float* W1   = (const float*)d_in[10];
    const float* b1   = (const float*)d_in[11];
    const float* W2   = (const float*)d_in[12];
    const float* b2   = (const float*)d_in[13];
    const float* ln2g = (const float*)d_in[14];
    const float* ln2b = (const float*)d_in[15];
    const float* Wlin = (const float*)d_in[16];
    const float* blin = (const float*)d_in[17];
    const float* Wtab = (const float*)d_in[18];
    const float* btab = (const float*)d_in[19];
    const float* Widx = (const float*)d_in[20];
    const float* bidx = (const float*)d_in[21];

    float* out     = (float*)d_out;
    float* out_tab = out;
    float* out_idx = out + (size_t)Bz*TOUTN*TBLV;

    float *x;
    __half *qkv, *xh, *ath, *ffh, *hcath, *hh;
    __half *Wqkvh, *Woh, *W1h, *W2h, *Wlinh;
    cudaGetSymbolAddress((void**)&x,    g_x);
    cudaGetSymbolAddress((void**)&qkv,  g_qkv);
    cudaGetSymbolAddress((void**)&xh,   g_xh);
    cudaGetSymbolAddress((void**)&ath,  g_ath);
    cudaGetSymbolAddress((void**)&ffh,  g_ffh);
    cudaGetSymbolAddress((void**)&hcath, g_hcath);
    cudaGetSymbolAddress((void**)&hh,   g_hh);
    cudaGetSymbolAddress((void**)&Wqkvh, g_Wqkvh);
    cudaGetSymbolAddress((void**)&Woh,   g_Woh);
    cudaGetSymbolAddress((void**)&W1h,   g_W1h);
    cudaGetSymbolAddress((void**)&W2h,   g_W2h);
    cudaGetSymbolAddress((void**)&Wlinh, g_Wlinh);

    cudaFuncSetAttribute(gemm_mma<1,false,true ,false,false>, cudaFuncAttributeMaxDynamicSharedMemorySize, GSMEM);
    cudaFuncSetAttribute(gemm_mma<1,false,false,false,true >, cudaFuncAttributeMaxDynamicSharedMemorySize, GSMEM);
    cudaFuncSetAttribute(gemm_mma<1,true, true, false,false>, cudaFuncAttributeMaxDynamicSharedMemorySize, GSMEM);
    cudaFuncSetAttribute(gemm_mma<TOUTN,false,false,true,false>, cudaFuncAttributeMaxDynamicSharedMemorySize, GSMEM);

    const int MT = NTOK / 128;  // 200
    const size_t sX   = (size_t)NTOK*Dm;
    const size_t sQKV = (size_t)NTOK*3*Dm;
    const size_t sFF  = (size_t)NTOK*DFF;

    {
        int n0 = 2*Ll*3*Dm*Dm, n1 = 2*Ll*Dm*Dm, n2 = 2*Ll*DFF*Dm,
            n3 = 2*Ll*Dm*DFF, n4 = HID*2*Dm;
        int tot = n0 + n1 + n2 + n3 + n4;
        cvt5_k<<<(tot + 255)/256, 256>>>(Wqkv, Wqkvh, n0, Wo, Woh, n1,
                                         W1, W1h, n2, W2, W2h, n3,
                                         Wlin, Wlinh, n4);
    }

    embed2_k<<<dim3(NTOK, 2), Dm>>>(tid_seq, iid_seq, tab_emb, idx_emb, x, xh);

    for (int l = 0; l < Ll; l++) {
        // qkv = x @ Wqkv^T + b  -> fp16
        gemm_mma<1,false,true,false,false><<<dim3(3, MT, 2), 256, GSMEM>>>(
            xh, Dm, sX,
            Wqkvh + (size_t)l*3*Dm*Dm, nullptr,
            Dm, (size_t)Ll*3*Dm*Dm,
            bqkv + (size_t)l*3*Dm, (size_t)Ll*3*Dm, nullptr, nullptr,
            nullptr, qkv, 3*Dm, sQKV, 3*Dm, Dm);

        attn_k<<<dim3(Bz*Hh, 2), ATT_THREADS>>>(qkv, ath);

        // x = LN(x + att @ Wo^T + bo)  -- fused epilogue
        gemm_mma<1,false,false,false,true><<<dim3(1, MT, 2), 256, GSMEM>>>(
            ath, Dm, sX,
            Woh + (size_t)l*Dm*Dm, nullptr,
            Dm, (size_t)Ll*Dm*Dm,
            bo + (size_t)l*Dm, (size_t)Ll*Dm,
            ln1g + (size_t)l*Dm, ln1b + (size_t)l*Dm,
            x, xh, Dm, sX, Dm, Dm);

        // ff = relu(x @ W1^T + b1) -> fp16
        gemm_mma<1,true,true,false,false><<<dim3(DFF/128, MT, 2), 256, GSMEM>>>(
            xh, Dm, sX,
            W1h + (size_t)l*DFF*Dm, nullptr,
            Dm, (size_t)Ll*DFF*Dm,
            b1 + (size_t)l*DFF, (size_t)Ll*DFF, nullptr, nullptr,
            nullptr, ffh, DFF, sFF, DFF, Dm);

        // x = LN(x + ff @ W2^T + b2)  -- fused epilogue
        gemm_mma<1,false,false,false,true><<<dim3(1, MT, 2), 256, GSMEM>>>(
            ffh, DFF, sFF,
            W2h + (size_t)l*Dm*DFF, nullptr,
            DFF, (size_t)Ll*Dm*DFF,
            b2 + (size_t)l*Dm, (size_t)Ll*Dm,
            ln2g + (size_t)l*Dm, ln2b + (size_t)l*Dm,
            x, xh, Dm, sX, Dm, DFF);
    }

    mean_k<<<dim3(Bz, 2), Dm>>>(x, hcath);

    // h = relu(hcat @ Wlin^T + blin) -> fp16   [128,512] K=256
    gemm_mma<1,true,true,false,false><<<dim3(HID/128, 1, 1), 256, GSMEM>>>(
        hcath, 2*Dm, 0, Wlinh, nullptr, 2*Dm, 0, blin, 0,
        nullptr, nullptr,
        nullptr, hh, HID, 0, HID, 2*Dm);

    // tab: [128,1000] + t-broadcast -> [1024,1000]
    gemm_mma<TOUTN,false,false,true,false><<<dim3((TBLV + 127)/128, 1, 1), 256, GSMEM>>>(
        hh, HID, 0, nullptr, Wtab, HID + 1, 0, btab, 0,
        nullptr, nullptr,
        out_tab, nullptr, TBLV, 0, TBLV, HID);

    // idx: [128,100000] + t-broadcast -> [1024,100000]
    gemm_mma<TOUTN,false,false,true,false><<<dim3((IDXV + 127)/128, 1, 1), 256, GSMEM>>>(
        hh, HID, 0, nullptr, Widx, HID + 1, 0, bidx, 0,
        nullptr, nullptr,
        out_idx, nullptr, IDXV, 0, IDXV, HID);
}